// round 14
// baseline (speedup 1.0000x reference)
#include <cuda_runtime.h>
#include <cuda_fp16.h>
#include <cstdint>

#define BB 8192
#define HH 100
#define TT 512
#define NOPSN 5
#define ZW 400
#define MROWS 64
#define NTHREADS 256
#define RSTRIDE 400   // bytes/row: 96 f16 hi (192B) + 96 f16 lo (192B) + 16B pad
#define LO_OFF 192

// smem byte offsets
#define SM_B    0                  // WhT hi/lo  [400][400]       = 160000
#define SM_WT   160000             // W tail fp32 [400][4]        = 6400
#define SM_A    166400             // h stage    [64][400]        = 25600
#define SM_HT   192000             // h tail fp32 [64][4]         = 1024
#define SM_EMB  193024             // float[6*400]                = 9600
#define SM_WOPS 202624             // float[500]                  = 2000
#define SM_PL   204624             // float[64*10]                = 2560
#define SM_OPS  207184             // int[64]                     = 256
#define SM_TOTAL 207440

__device__ float g_xW0[(size_t)BB * ZW];   // x0@Wx, permuted cols
__device__ float g_embW[6 * ZW];           // emb@Wx, permuted cols

// storage col j -> original col (j%4)*100 + j/4 (gate-interleaved)
__device__ __host__ __forceinline__ int permCol(int j) { return (j & 3) * 100 + (j >> 2); }

__device__ __forceinline__ float tanha(float x) {
    float y; asm("tanh.approx.f32 %0, %1;" : "=f"(y) : "f"(x)); return y;
}
__device__ __forceinline__ float fsig(float x) { return fmaf(0.5f, tanha(0.5f * x), 0.5f); }

__device__ __forceinline__ uint32_t smem_u32(const void* p) {
    uint32_t a;
    asm("{ .reg .u64 t; cvta.to.shared.u64 t, %1; cvt.u32.u64 %0, t; }" : "=r"(a) : "l"(p));
    return a;
}
__device__ __forceinline__ void ldsm4(uint32_t& r0, uint32_t& r1, uint32_t& r2, uint32_t& r3, uint32_t a) {
    asm volatile("ldmatrix.sync.aligned.m8n8.x4.shared.b16 {%0,%1,%2,%3}, [%4];"
                 : "=r"(r0), "=r"(r1), "=r"(r2), "=r"(r3) : "r"(a));
}
__device__ __forceinline__ void mma16816(float& d0, float& d1, float& d2, float& d3,
                                         uint32_t a0, uint32_t a1, uint32_t a2, uint32_t a3,
                                         uint32_t b0, uint32_t b1) {
    asm volatile("mma.sync.aligned.m16n8k16.row.col.f32.f16.f16.f32 "
                 "{%0,%1,%2,%3}, {%4,%5,%6,%7}, {%8,%9}, {%0,%1,%2,%3};"
                 : "+f"(d0), "+f"(d1), "+f"(d2), "+f"(d3)
                 : "r"(a0), "r"(a1), "r"(a2), "r"(a3), "r"(b0), "r"(b1));
}
// f16-accumulator variant: D,C are 2 x .f16x2 regs
__device__ __forceinline__ void mma16816h(uint32_t& d0, uint32_t& d1,
                                          uint32_t a0, uint32_t a1, uint32_t a2, uint32_t a3,
                                          uint32_t b0, uint32_t b1) {
    asm volatile("mma.sync.aligned.m16n8k16.row.col.f16.f16.f16.f16 "
                 "{%0,%1}, {%2,%3,%4,%5}, {%6,%7}, {%0,%1};"
                 : "+r"(d0), "+r"(d1)
                 : "r"(a0), "r"(a1), "r"(a2), "r"(a3), "r"(b0), "r"(b1));
}
__device__ __forceinline__ void pairbar(int id) {
    asm volatile("bar.sync %0, 64;" :: "r"(id) : "memory");
}
__device__ __forceinline__ float2 h2f2(uint32_t v) {
    __half2 h = *reinterpret_cast<__half2*>(&v);
    return __half22float2(h);
}

__global__ void embW_kernel(const float* __restrict__ emb, const float* __restrict__ Wx) {
    int j = threadIdx.x;
    if (j >= ZW) return;
    int pj = permCol(j);
    for (int e = 0; e < 6; ++e) {
        float acc = 0.f;
        #pragma unroll 4
        for (int k = 0; k < HH; ++k) acc = fmaf(emb[e * HH + k], Wx[k * ZW + pj], acc);
        g_embW[e * ZW + j] = acc;
    }
}

__global__ void xw0_kernel(const float* __restrict__ x0, const float* __restrict__ Wx) {
    __shared__ float xs[HH];
    int b = blockIdx.x;
    for (int i = threadIdx.x; i < HH; i += blockDim.x) xs[i] = x0[b * HH + i];
    __syncthreads();
    for (int j = threadIdx.x; j < ZW; j += blockDim.x) {
        int pj = permCol(j);
        float acc = 0.f;
        #pragma unroll 4
        for (int k = 0; k < HH; ++k) acc = fmaf(xs[k], Wx[k * ZW + pj], acc);
        g_xW0[(size_t)b * ZW + j] = acc;
    }
}

__global__ void __launch_bounds__(NTHREADS, 1)
rnn_main(const float* __restrict__ Wh, const float* __restrict__ Wops,
         const float* __restrict__ upt, float* __restrict__ out)
{
    extern __shared__ char smb[];
    const uint32_t sb = smem_u32(smb);
    float* sEmbF = (float*)(smb + SM_EMB);
    float* sWops = (float*)(smb + SM_WOPS);
    float* sPL   = (float*)(smb + SM_PL);
    int*   sOps  = (int*)(smb + SM_OPS);
    float* sHT   = (float*)(smb + SM_HT);

    const int tid = threadIdx.x, wid = tid >> 5, lane = tid & 31;

    // ---- one-time init: B = Wh^T f16 hi/lo (k 0..95), fp32 tail (k 96..99) ----
    for (int idx = tid; idx < 400 * 96; idx += NTHREADS) {
        int n = idx / 96, k = idx - n * 96;
        float w = Wh[k * ZW + permCol(n)];
        __half hh = __float2half_rn(w);
        __half hl = __float2half_rn(w - __half2float(hh));
        *(__half*)(smb + SM_B + n * RSTRIDE + k * 2) = hh;
        *(__half*)(smb + SM_B + n * RSTRIDE + LO_OFF + k * 2) = hl;
    }
    for (int i = tid; i < 400 * 4; i += NTHREADS) {
        int n = i >> 2, kk = i & 3;
        ((float*)(smb + SM_WT))[n * 4 + kk] = Wh[(96 + kk) * ZW + permCol(n)];
    }
    // zero A stage + h tail (h(-1) = 0)
    for (int i = tid; i < (MROWS * RSTRIDE) / 4; i += NTHREADS)
        ((uint32_t*)(smb + SM_A))[i] = 0u;
    for (int i = tid; i < MROWS * 4; i += NTHREADS) sHT[i] = 0.f;
    for (int i = tid; i < 6 * ZW; i += NTHREADS) sEmbF[i] = g_embW[i];
    for (int i = tid; i < HH * NOPSN; i += NTHREADS) sWops[i] = Wops[i];
    __syncthreads();

    const int mt = wid & 3, nh = wid >> 2;
    const int gr = lane >> 2, cq = lane & 3;
    const bool even = ((lane & 1) == 0);
    const int m0 = mt * 16;
    const int R0l = m0 + gr, R1l = R0l + 8;
    const int jbase = nh * 25;
    const int barid = 1 + mt;
    // epilogue split: each warp of the pair handles 8 rows of its slab
    const bool epi = (lane < 8);
    const int erow = m0 + nh * 8 + (lane & 7);

    // A-frag lane addressing (ldmatrix x4 groups)
    const int lr = lane & 7, gg = lane >> 3;
    const uint32_t aAddrHi = sb + SM_A + (uint32_t)(m0 + lr + (gg & 1) * 8) * RSTRIDE + (gg >> 1) * 16;
    // B-frag lane addressing: groups = {hi k0, hi k0+8, lo k0, lo k0+8}
    const uint32_t bOffLane = (uint32_t)lr * RSTRIDE + (gg & 1) * 16 + (gg >> 1) * LO_OFF;

    float cS[25];
    #pragma unroll
    for (int i = 0; i < 25; ++i) cS[i] = 0.f;
    float accLP = 0.f, accENT = 0.f;

    for (int t = 0; t < TT; ++t) {
        // gumbel inputs for this lane's epilogue row
        float un[NOPSN];
        if (epi) {
            const float* up = upt + ((size_t)t * BB + blockIdx.x * MROWS + erow) * NOPSN;
            #pragma unroll
            for (int n = 0; n < NOPSN; ++n) un[n] = up[n];
        }

        pairbar(barid);   // bar0: h(t-1) stage + tail + sOps(t-1) stable for this slab

        // per-row xW pointers
        const float *p0, *p1;
        if (t == 0) {
            p0 = g_xW0 + (size_t)(blockIdx.x * MROWS + R0l) * ZW;
            p1 = g_xW0 + (size_t)(blockIdx.x * MROWS + R1l) * ZW;
        } else {
            p0 = sEmbF + sOps[R0l] * ZW;
            p1 = sEmbF + sOps[R1l] * ZW;
        }
        // fp32 h tails for this lane's two rows (units 96..99 of h(t-1))
        float4 hT0 = *(float4*)(smb + SM_HT + R0l * 16);
        float4 hT1 = *(float4*)(smb + SM_HT + R1l * 16);

        // ---- load A fragments (h(t-1) hi/lo), 6 k-steps ----
        uint32_t ahi[24], alo[24];
        #pragma unroll
        for (int kk = 0; kk < 6; ++kk) {
            ldsm4(ahi[4 * kk], ahi[4 * kk + 1], ahi[4 * kk + 2], ahi[4 * kk + 3], aAddrHi + kk * 32);
            ldsm4(alo[4 * kk], alo[4 * kk + 1], alo[4 * kk + 2], alo[4 * kk + 3], aAddrHi + LO_OFF + kk * 32);
        }
        pairbar(barid);   // bar1: slab A reads done; safe to overwrite with h(t)

        float pl[NOPSN] = {0.f, 0.f, 0.f, 0.f, 0.f};

        #pragma unroll
        for (int jj = 0; jj < 25; ++jj) {
            const int n0 = 8 * (jbase + jj);
            const uint32_t bb = sb + SM_B + (uint32_t)n0 * RSTRIDE + bOffLane;
            // pass A: f32 accumulate (full magnitude); passes B,C: f16 accumulate (corrections)
            float A0 = 0.f, A1 = 0.f, A2 = 0.f, A3 = 0.f;
            uint32_t Bh0 = 0u, Bh1 = 0u;   // ahi*blo
            uint32_t Ch0 = 0u, Ch1 = 0u;   // alo*bhi
            #pragma unroll
            for (int kk = 0; kk < 6; ++kk) {
                uint32_t bh0, bh1, bl0, bl1;
                ldsm4(bh0, bh1, bl0, bl1, bb + kk * 32);
                mma16816(A0, A1, A2, A3, ahi[4 * kk], ahi[4 * kk + 1], ahi[4 * kk + 2], ahi[4 * kk + 3], bh0, bh1);
                mma16816h(Bh0, Bh1, ahi[4 * kk], ahi[4 * kk + 1], ahi[4 * kk + 2], ahi[4 * kk + 3], bl0, bl1);
                mma16816h(Ch0, Ch1, alo[4 * kk], alo[4 * kk + 1], alo[4 * kk + 2], alo[4 * kk + 3], bh0, bh1);
            }
            const int col0 = n0 + 2 * cq;
            // exact fp32 tail: units 96..99
            const float4 w0 = *(const float4*)(smb + SM_WT + col0 * 16);
            const float4 w1 = *(const float4*)(smb + SM_WT + col0 * 16 + 16);
            float t0 = hT0.x * w0.x + hT0.y * w0.y + hT0.z * w0.z + hT0.w * w0.w;
            float t1 = hT0.x * w1.x + hT0.y * w1.y + hT0.z * w1.z + hT0.w * w1.w;
            float t2 = hT1.x * w0.x + hT1.y * w0.y + hT1.z * w0.z + hT1.w * w0.w;
            float t3 = hT1.x * w1.x + hT1.y * w1.y + hT1.z * w1.z + hT1.w * w1.w;
            float2 b0f = h2f2(Bh0), b1f = h2f2(Bh1);
            float2 c0f = h2f2(Ch0), c1f = h2f2(Ch1);
            float z0 = (A0 + b0f.x + c0f.x) + t0 + p0[col0];
            float z1 = (A1 + b0f.y + c0f.y) + t1 + p0[col0 + 1];
            float z2 = (A2 + b1f.x + c1f.x) + t2 + p1[col0];
            float z3 = (A3 + b1f.y + c1f.y) + t3 + p1[col0 + 1];
            float o0 = __shfl_xor_sync(0xffffffffu, z0, 1);
            float o1 = __shfl_xor_sync(0xffffffffu, z1, 1);
            float o2 = __shfl_xor_sync(0xffffffffu, z2, 1);
            float o3 = __shfl_xor_sync(0xffffffffu, z3, 1);
            // even lane: row R0 gates (i,f)=own(z0,z1), (c,o)=partner(o0,o1)
            // odd  lane: row R1 gates (i,f)=partner(o2,o3), (c,o)=own(z2,z3)
            float zi = even ? z0 : o2;
            float zf = even ? z1 : o3;
            float zc = even ? o0 : z2;
            float zo = even ? o1 : z3;
            float cn = fsig(zf) * cS[jj] + fsig(zi) * tanha(zc);
            cS[jj] = cn;
            float hn = fsig(zo) * tanha(cn);
            const int u = 2 * (jbase + jj) + (cq >> 1);
            const int myrow = even ? R0l : R1l;
            if (u < 96) {
                __half hh = __float2half_rn(hn);
                __half hl = __float2half_rn(hn - __half2float(hh));
                *(__half*)(smb + SM_A + myrow * RSTRIDE + u * 2) = hh;
                *(__half*)(smb + SM_A + myrow * RSTRIDE + LO_OFF + u * 2) = hl;
            } else {
                sHT[myrow * 4 + (u - 96)] = hn;   // exact fp32 tail
            }
            const float* wp = sWops + u * NOPSN;
            pl[0] = fmaf(hn, wp[0], pl[0]);
            pl[1] = fmaf(hn, wp[1], pl[1]);
            pl[2] = fmaf(hn, wp[2], pl[2]);
            pl[3] = fmaf(hn, wp[3], pl[3]);
            pl[4] = fmaf(hn, wp[4], pl[4]);
        }

        // combine unit-partials within warp: lanes {4g,4g+2} -> row R0, {4g+1,4g+3} -> row R1
        #pragma unroll
        for (int n = 0; n < NOPSN; ++n)
            pl[n] += __shfl_xor_sync(0xffffffffu, pl[n], 2);
        if (cq < 2) {
            int rw = (cq == 0) ? R0l : R1l;
            #pragma unroll
            for (int n = 0; n < NOPSN; ++n)
                sPL[rw * 10 + nh * NOPSN + n] = pl[n];
        }
        pairbar(barid);   // bar2: slab sPL + h(t) complete

        // ---- sampling / log-softmax epilogue (accurate libm; 8 lanes per warp) ----
        if (epi) {
            int b = blockIdx.x * MROWS + erow;
            float lg[NOPSN];
            #pragma unroll
            for (int n = 0; n < NOPSN; ++n) {
                float s = sPL[erow * 10 + n] + sPL[erow * 10 + NOPSN + n];
                lg[n] = 1.5f * tanhf(s);
            }
            int op = 0;
            float best = 0.f, mx = lg[0], lsel = lg[0];
            #pragma unroll
            for (int n = 0; n < NOPSN; ++n) {
                float gum = -logf(-logf(un[n] + 1e-9f) + 1e-9f);
                float v = lg[n] + gum;
                if (n == 0) { best = v; }
                else if (v > best) { best = v; op = n; lsel = lg[n]; }
                if (lg[n] > mx) mx = lg[n];
            }
            float ss = 0.f;
            #pragma unroll
            for (int n = 0; n < NOPSN; ++n) ss += expf(lg[n] - mx);
            float lse = mx + logf(ss);
            float cur = lse - lsel;
            float ent = cur * expf(-cur);
            accLP += cur; accENT += ent;
            sOps[erow] = op;
            out[2 * (size_t)BB + (size_t)t * BB + b] = (float)op;
        }
    }

    if (epi) {
        int b = blockIdx.x * MROWS + erow;
        out[b] = accLP;
        out[BB + b] = accENT;
    }
}

extern "C" void kernel_launch(void* const* d_in, const int* in_sizes, int n_in,
                              void* d_out, int out_size) {
    const float* x0  = (const float*)d_in[0];
    const float* Wx  = (const float*)d_in[1];
    const float* Wh  = (const float*)d_in[2];
    const float* Wop = (const float*)d_in[3];
    const float* emb = (const float*)d_in[4];
    const float* u   = (const float*)d_in[5];
    float* out = (float*)d_out;

    cudaFuncSetAttribute(rnn_main, cudaFuncAttributeMaxDynamicSharedMemorySize, SM_TOTAL);

    embW_kernel<<<1, ZW>>>(emb, Wx);
    xw0_kernel<<<BB, 128>>>(x0, Wx);
    rnn_main<<<BB / MROWS, NTHREADS, SM_TOTAL>>>(Wh, Wop, u, out);
}